// round 6
// baseline (speedup 1.0000x reference)
#include <cuda_runtime.h>
#include <cuda_bf16.h>
#include <cstdint>

// Static scratch (no allocations allowed). Sized for V <= 4M, n_he <= 8M.
__device__ int g_counts[4u << 20];      // histogram
__device__ int g_offsets[4u << 20];     // block-local excl offsets -> incl ends
__device__ int g_blocksums[4096];       // global exclusive block offsets
__device__ int g_perm[8u << 20];        // edge indices grouped by vertex

// ---------------------------------------------------------------------------
// Warp-shuffle inclusive scan helper.
// ---------------------------------------------------------------------------
__device__ __forceinline__ int warp_incl_scan(int v)
{
    #pragma unroll
    for (int d = 1; d < 32; d <<= 1) {
        int t = __shfl_up_sync(0xffffffffu, v, d);
        if ((threadIdx.x & 31) >= d) v += t;
    }
    return v;
}

// ---------------------------------------------------------------------------
// Pass A: histogram of vertex ids (int4-vectorized id stream).
// ---------------------------------------------------------------------------
__global__ void hist_kernel(const int4* __restrict__ ids4, int nq,
                            const int* __restrict__ ids, int n)
{
    int i = blockIdx.x * blockDim.x + threadIdx.x;
    if (i < nq) {
        int4 v = __ldg(ids4 + i);
        atomicAdd(&g_counts[v.x], 1);
        atomicAdd(&g_counts[v.y], 1);
        atomicAdd(&g_counts[v.z], 1);
        atomicAdd(&g_counts[v.w], 1);
    }
    if (i == 0) {
        for (int j = nq * 4; j < n; j++) atomicAdd(&g_counts[__ldg(ids + j)], 1);
    }
}

// ---------------------------------------------------------------------------
// Scan step 1: per-block (1024) exclusive scan of counts; block totals out.
// g_offsets gets BLOCK-LOCAL exclusive offsets.
// ---------------------------------------------------------------------------
__global__ void scan1_kernel(int V)
{
    __shared__ int wsum[32];
    int i = blockIdx.x * 1024 + threadIdx.x;
    int v = (i < V) ? g_counts[i] : 0;
    int incl = warp_incl_scan(v);
    int lane = threadIdx.x & 31, wid = threadIdx.x >> 5;
    if (lane == 31) wsum[wid] = incl;
    __syncthreads();
    if (wid == 0) {
        int w = wsum[lane];
        int ws = warp_incl_scan(w);
        wsum[lane] = ws - w;                  // exclusive warp offsets
    }
    __syncthreads();
    int excl = incl - v + wsum[wid];
    if (i < V) g_offsets[i] = excl;
    if (threadIdx.x == 1023) g_blocksums[blockIdx.x] = excl + v;   // block total
}

// ---------------------------------------------------------------------------
// Scan step 2: single-block exclusive scan of block sums (carry loop).
// ---------------------------------------------------------------------------
__global__ void scan2_kernel(int nb)
{
    __shared__ int wsum[32];
    __shared__ int carry_s;
    if (threadIdx.x == 0) carry_s = 0;
    __syncthreads();
    for (int base = 0; base < nb; base += 1024) {
        int i = base + threadIdx.x;
        int v = (i < nb) ? g_blocksums[i] : 0;
        int incl = warp_incl_scan(v);
        int lane = threadIdx.x & 31, wid = threadIdx.x >> 5;
        if (lane == 31) wsum[wid] = incl;
        __syncthreads();
        if (wid == 0) {
            int w = wsum[lane];
            int ws = warp_incl_scan(w);
            wsum[lane] = ws - w;
        }
        __syncthreads();
        int excl = incl - v + wsum[wid] + carry_s;
        if (i < nb) g_blocksums[i] = excl;
        __syncthreads();
        if (threadIdx.x == 1023) carry_s = excl + v;
        __syncthreads();
    }
}

// ---------------------------------------------------------------------------
// Pass B: counting-sort of edge INDICES by vertex id. Global position =
// block-local cursor bump + global block offset (blocksums is 4KB, cached).
// Post: g_offsets[v] == block-local inclusive end of segment v.
// ---------------------------------------------------------------------------
__global__ void perm_kernel(const int4* __restrict__ ids4, int nq,
                            const int* __restrict__ ids, int n)
{
    int i = blockIdx.x * blockDim.x + threadIdx.x;
    if (i < nq) {
        int4 v = __ldg(ids4 + i);
        int p0 = atomicAdd(&g_offsets[v.x], 1) + __ldg(&g_blocksums[v.x >> 10]);
        int p1 = atomicAdd(&g_offsets[v.y], 1) + __ldg(&g_blocksums[v.y >> 10]);
        int p2 = atomicAdd(&g_offsets[v.z], 1) + __ldg(&g_blocksums[v.z >> 10]);
        int p3 = atomicAdd(&g_offsets[v.w], 1) + __ldg(&g_blocksums[v.w >> 10]);
        g_perm[p0] = i * 4;
        g_perm[p1] = i * 4 + 1;
        g_perm[p2] = i * 4 + 2;
        g_perm[p3] = i * 4 + 3;
    }
    if (i == 0) {
        for (int j = nq * 4; j < n; j++) {
            int v = __ldg(ids + j);
            int p = atomicAdd(&g_offsets[v], 1) + __ldg(&g_blocksums[v >> 10]);
            g_perm[p] = j;
        }
    }
}

// ---------------------------------------------------------------------------
// Pass C: gather + mean. 8 threads per vertex; thread s covers feature quad s.
// Per 8-edge chunk: thread s loads ONE perm entry (coalesced) and the group
// exchanges via group-masked shfl (the 8 lanes of a group share v, so they
// are always converged; other groups are excluded from the mask).
// All 8 row loads per chunk are independent -> high MLP, no serial tail for
// deg <= 8 (~85% of Poisson(6) vertices).
// ---------------------------------------------------------------------------
__global__ void gather_kernel(const float4* __restrict__ x4,
                              float4* __restrict__ out4, int V)
{
    long long t = (long long)blockIdx.x * blockDim.x + threadIdx.x;
    int v = (int)(t >> 3);          // vertex
    int s = (int)(t & 7);           // quad index within the 32-dim row
    if (v >= V) return;             // whole 8-thread group exits together

    int lane = threadIdx.x & 31;
    unsigned gbase = lane & ~7u;                  // group's lane base
    unsigned gmask = 0xFFu << gbase;              // group-local shfl mask

    int beg = (v == 0) ? 0
            : __ldg(&g_offsets[v - 1]) + __ldg(&g_blocksums[(v - 1) >> 10]);
    int end = __ldg(&g_offsets[v]) + __ldg(&g_blocksums[v >> 10]);
    int deg = end - beg;

    float4 acc = make_float4(0.f, 0.f, 0.f, 0.f);

    for (int base = beg; base < end; base += 8) {
        int j = base + s;
        int e_s = (j < end) ? __ldg(&g_perm[j]) : -1;
        #pragma unroll
        for (int u = 0; u < 8; u++) {
            int e = __shfl_sync(gmask, e_s, gbase + u);
            if (e >= 0) {
                float4 a = __ldg(x4 + (long long)e * 8 + s);
                acc.x += a.x; acc.y += a.y; acc.z += a.z; acc.w += a.w;
            }
        }
    }

    float inv = 1.0f / fmaxf((float)deg, 1.0f);
    out4[(long long)v * 8 + s] =
        make_float4(acc.x * inv, acc.y * inv, acc.z * inv, acc.w * inv);
}

extern "C" void kernel_launch(void* const* d_in, const int* in_sizes, int n_in,
                              void* d_out, int out_size)
{
    const float4* x4  = (const float4*)d_in[0];
    const int*    ids = (const int*)d_in[1];

    int n_he = in_sizes[1];                     // element count of vertex_ids
    int V    = (int)((long long)out_size / 32); // output is [V, 32]
    int nq   = n_he >> 2;                       // int4 quads in the id stream

    // Zero the histogram.
    void* counts_ptr = nullptr;
    cudaGetSymbolAddress(&counts_ptr, g_counts);
    cudaMemsetAsync(counts_ptr, 0, (size_t)V * sizeof(int));

    // Pass A: histogram (vectorized).
    hist_kernel<<<(nq + 255) / 256, 256>>>((const int4*)ids, nq, ids, n_he);

    // Exclusive scan (block-local offsets + global block offsets).
    int nb = (V + 1023) / 1024;
    scan1_kernel<<<nb, 1024>>>(V);
    scan2_kernel<<<1, 1024>>>(nb);

    // Pass B: permutation (vectorized).
    perm_kernel<<<(nq + 255) / 256, 256>>>((const int4*)ids, nq, ids, n_he);

    // Pass C: gather + mean, 8 threads per vertex.
    {
        long long total = (long long)V * 8;
        int threads = 256;
        int blocks = (int)((total + threads - 1) / threads);
        gather_kernel<<<blocks, threads>>>(x4, (float4*)d_out, V);
    }
}

// round 7
// speedup vs baseline: 1.2094x; 1.2094x over previous
#include <cuda_runtime.h>
#include <cuda_bf16.h>
#include <cstdint>

// Static scratch (no allocations allowed). Sized for V <= 4M, n_he <= 8M.
__device__ int g_counts[4u << 20];      // histogram
__device__ int g_offsets[4u << 20];     // block-local excl offsets -> incl ends
__device__ int g_blocksums[4096];       // global exclusive block offsets
__device__ int g_perm[8u << 20];        // edge indices grouped by vertex

// ---------------------------------------------------------------------------
// Warp-shuffle inclusive scan helper.
// ---------------------------------------------------------------------------
__device__ __forceinline__ int warp_incl_scan(int v)
{
    #pragma unroll
    for (int d = 1; d < 32; d <<= 1) {
        int t = __shfl_up_sync(0xffffffffu, v, d);
        if ((threadIdx.x & 31) >= d) v += t;
    }
    return v;
}

// ---------------------------------------------------------------------------
// Pass A: histogram of vertex ids (int4-vectorized id stream).
// ---------------------------------------------------------------------------
__global__ void hist_kernel(const int4* __restrict__ ids4, int nq,
                            const int* __restrict__ ids, int n)
{
    int i = blockIdx.x * blockDim.x + threadIdx.x;
    if (i < nq) {
        int4 v = __ldg(ids4 + i);
        atomicAdd(&g_counts[v.x], 1);
        atomicAdd(&g_counts[v.y], 1);
        atomicAdd(&g_counts[v.z], 1);
        atomicAdd(&g_counts[v.w], 1);
    }
    if (i == 0) {
        for (int j = nq * 4; j < n; j++) atomicAdd(&g_counts[__ldg(ids + j)], 1);
    }
}

// ---------------------------------------------------------------------------
// Scan step 1: per-block (1024) exclusive scan of counts; block totals out.
// g_offsets gets BLOCK-LOCAL exclusive offsets.
// ---------------------------------------------------------------------------
__global__ void scan1_kernel(int V)
{
    __shared__ int wsum[32];
    int i = blockIdx.x * 1024 + threadIdx.x;
    int v = (i < V) ? g_counts[i] : 0;
    int incl = warp_incl_scan(v);
    int lane = threadIdx.x & 31, wid = threadIdx.x >> 5;
    if (lane == 31) wsum[wid] = incl;
    __syncthreads();
    if (wid == 0) {
        int w = wsum[lane];
        int ws = warp_incl_scan(w);
        wsum[lane] = ws - w;                  // exclusive warp offsets
    }
    __syncthreads();
    int excl = incl - v + wsum[wid];
    if (i < V) g_offsets[i] = excl;
    if (threadIdx.x == 1023) g_blocksums[blockIdx.x] = excl + v;   // block total
}

// ---------------------------------------------------------------------------
// Scan step 2: single-block exclusive scan of block sums (carry loop).
// After this, g_blocksums[b] == global exclusive offset of 1024-vertex block b.
// ---------------------------------------------------------------------------
__global__ void scan2_kernel(int nb)
{
    __shared__ int wsum[32];
    __shared__ int carry_s;
    if (threadIdx.x == 0) carry_s = 0;
    __syncthreads();
    for (int base = 0; base < nb; base += 1024) {
        int i = base + threadIdx.x;
        int v = (i < nb) ? g_blocksums[i] : 0;
        int incl = warp_incl_scan(v);
        int lane = threadIdx.x & 31, wid = threadIdx.x >> 5;
        if (lane == 31) wsum[wid] = incl;
        __syncthreads();
        if (wid == 0) {
            int w = wsum[lane];
            int ws = warp_incl_scan(w);
            wsum[lane] = ws - w;
        }
        __syncthreads();
        int excl = incl - v + wsum[wid] + carry_s;
        if (i < nb) g_blocksums[i] = excl;
        __syncthreads();
        if (threadIdx.x == 1023) carry_s = excl + v;
        __syncthreads();
    }
}

// ---------------------------------------------------------------------------
// Pass B: counting-sort of edge INDICES by vertex id (scalar, one returning
// atomic per thread — maximizes independent atomic streams). Global position
// = block-local cursor bump + global block offset (4KB table, L1-resident).
// Post: g_offsets[v] == block-local inclusive end of segment v.
// ---------------------------------------------------------------------------
__global__ void perm_kernel(const int* __restrict__ ids, int n)
{
    int i = blockIdx.x * blockDim.x + threadIdx.x;
    if (i < n) {
        int v = __ldg(ids + i);
        int pos = atomicAdd(&g_offsets[v], 1) + __ldg(&g_blocksums[v >> 10]);
        g_perm[pos] = i;
    }
}

// ---------------------------------------------------------------------------
// Pass C: gather + mean. 8 threads per vertex; thread s covers feature quad s
// as one float4 (group of 8 threads = one 128B edge row per load).
// Per 8-edge chunk every thread loads all 8 perm entries (one DRAM/L2 fetch,
// 7 L1-broadcast hits) so each row load's address chain is load->load, no
// shuffle hop. All 8 row loads are independent -> high MLP; no serial tail
// for deg <= 8 (~85% of Poisson(6) vertices).
// ---------------------------------------------------------------------------
__global__ void gather_kernel(const float4* __restrict__ x4,
                              float4* __restrict__ out4, int V)
{
    long long t = (long long)blockIdx.x * blockDim.x + threadIdx.x;
    int v = (int)(t >> 3);          // vertex
    int s = (int)(t & 7);           // quad index within the 32-dim row
    if (v >= V) return;

    int beg = (v == 0) ? 0
            : __ldg(&g_offsets[v - 1]) + __ldg(&g_blocksums[(v - 1) >> 10]);
    int end = __ldg(&g_offsets[v]) + __ldg(&g_blocksums[v >> 10]);
    int deg = end - beg;

    float4 acc = make_float4(0.f, 0.f, 0.f, 0.f);

    for (int base = beg; base < end; base += 8) {
        int e[8];
        #pragma unroll
        for (int u = 0; u < 8; u++) {
            int j = base + u;
            e[u] = (j < end) ? __ldg(&g_perm[j]) : -1;
        }
        #pragma unroll
        for (int u = 0; u < 8; u++) {
            if (e[u] >= 0) {
                float4 a = __ldg(x4 + (long long)e[u] * 8 + s);
                acc.x += a.x; acc.y += a.y; acc.z += a.z; acc.w += a.w;
            }
        }
    }

    float inv = 1.0f / fmaxf((float)deg, 1.0f);
    out4[(long long)v * 8 + s] =
        make_float4(acc.x * inv, acc.y * inv, acc.z * inv, acc.w * inv);
}

extern "C" void kernel_launch(void* const* d_in, const int* in_sizes, int n_in,
                              void* d_out, int out_size)
{
    const float4* x4  = (const float4*)d_in[0];
    const int*    ids = (const int*)d_in[1];

    int n_he = in_sizes[1];                     // element count of vertex_ids
    int V    = (int)((long long)out_size / 32); // output is [V, 32]
    int nq   = n_he >> 2;                       // int4 quads in the id stream

    // Zero the histogram.
    void* counts_ptr = nullptr;
    cudaGetSymbolAddress(&counts_ptr, g_counts);
    cudaMemsetAsync(counts_ptr, 0, (size_t)V * sizeof(int));

    // Pass A: histogram (vectorized id stream).
    hist_kernel<<<(nq + 255) / 256, 256>>>((const int4*)ids, nq, ids, n_he);

    // Exclusive scan: block-local offsets + global block offsets (no scan3).
    int nb = (V + 1023) / 1024;
    scan1_kernel<<<nb, 1024>>>(V);
    scan2_kernel<<<1, 1024>>>(nb);

    // Pass B: permutation (scalar atomics, blocksums folded in).
    perm_kernel<<<(n_he + 255) / 256, 256>>>(ids, n_he);

    // Pass C: gather + mean, 8 threads per vertex.
    {
        long long total = (long long)V * 8;
        int threads = 256;
        int blocks = (int)((total + threads - 1) / threads);
        gather_kernel<<<blocks, threads>>>(x4, (float4*)d_out, V);
    }
}